// round 1
// baseline (speedup 1.0000x reference)
#include <cuda_runtime.h>
#include <math.h>

// Problem constants: B=131072, D=512, N=1.
// loss_b = log1p(exp((dot(img,neg) - dot(img,pos)) / 50)); output = mean_b loss_b.
// (cosine-sim/argmax branch is identity for N==1.)

#define B_TOTAL 131072
#define D_F4 128              // 512 floats = 128 float4 per row
#define WARPS_PER_BLOCK 8
#define THREADS 256
#define NSLOTS 256

__device__ float g_partial[NSLOTS];

__global__ void zero_partials_kernel() {
    g_partial[threadIdx.x] = 0.0f;
}

__global__ __launch_bounds__(THREADS) void loss_main_kernel(
    const float4* __restrict__ img,
    const float4* __restrict__ pos,
    const float4* __restrict__ neg)
{
    const int wid  = threadIdx.x >> 5;
    const int lane = threadIdx.x & 31;
    const size_t row  = (size_t)blockIdx.x * WARPS_PER_BLOCK + wid;
    const size_t base = row * D_F4 + lane;

    float dp = 0.0f, dn = 0.0f;
#pragma unroll
    for (int i = 0; i < 4; i++) {
        const float4 a = __ldg(img + base + i * 32);
        const float4 p = __ldg(pos + base + i * 32);
        const float4 n = __ldg(neg + base + i * 32);
        dp += a.x * p.x + a.y * p.y + a.z * p.z + a.w * p.w;
        dn += a.x * n.x + a.y * n.y + a.z * n.z + a.w * n.w;
    }

    // warp reduce both dots
#pragma unroll
    for (int off = 16; off; off >>= 1) {
        dp += __shfl_xor_sync(0xffffffffu, dp, off);
        dn += __shfl_xor_sync(0xffffffffu, dn, off);
    }

    __shared__ float s_loss[WARPS_PER_BLOCK];
    if (lane == 0) {
        // -log(ep/(ep+en)) == log1p(exp((dn-dp)/50))
        s_loss[wid] = log1pf(expf((dn - dp) * 0.02f));
    }
    __syncthreads();

    if (threadIdx.x == 0) {
        float sum = 0.0f;
#pragma unroll
        for (int i = 0; i < WARPS_PER_BLOCK; i++) sum += s_loss[i];
        atomicAdd(&g_partial[blockIdx.x & (NSLOTS - 1)], sum);
    }
}

__global__ void finalize_kernel(float* __restrict__ out) {
    const int t = threadIdx.x;
    float v = g_partial[t];
#pragma unroll
    for (int off = 16; off; off >>= 1)
        v += __shfl_xor_sync(0xffffffffu, v, off);

    __shared__ float s[NSLOTS / 32];
    if ((t & 31) == 0) s[t >> 5] = v;
    __syncthreads();

    if (t < NSLOTS / 32) {
        float w = s[t];
#pragma unroll
        for (int off = (NSLOTS / 64); off; off >>= 1)
            w += __shfl_xor_sync(0x000000ffu, w, off);
        if (t == 0) out[0] = w / (float)B_TOTAL;
    }
}

extern "C" void kernel_launch(void* const* d_in, const int* in_sizes, int n_in,
                              void* d_out, int out_size) {
    (void)in_sizes; (void)n_in; (void)out_size;
    const float4* img = (const float4*)d_in[0];
    const float4* pos = (const float4*)d_in[1];
    const float4* neg = (const float4*)d_in[2];
    float* out = (float*)d_out;

    zero_partials_kernel<<<1, NSLOTS>>>();
    loss_main_kernel<<<B_TOTAL / WARPS_PER_BLOCK, THREADS>>>(img, pos, neg);
    finalize_kernel<<<1, NSLOTS>>>(out);
}